// round 10
// baseline (speedup 1.0000x reference)
#include <cuda_runtime.h>
#include <cuda_bf16.h>

#define Bc 8
#define Nc 8192
#define Sc 1024
#define Kc 32
#define Pc (Bc*Sc*Kc)   // 262144 total grouped points
#define CLS 2           // FPS cluster size

// ---------------- scratch (static device globals; no allocation) ----------------
__device__ float  g_h0[3*Pc];          // centered grouped coords, [c][P]
__device__ float  g_y1[64*Pc];         // 64 MiB
__device__ float  g_y2[64*Pc];         // 64 MiB
__device__ float  g_max3[Bc*Sc*128];   // per-centroid per-channel max of y3 (4 MiB)
__device__ float  g_min3[Bc*Sc*128];   // per-centroid per-channel min of y3 (4 MiB)
__device__ double g_sums[3][128][2];   // per-layer per-channel (sum, sumsq)
__device__ float  g_stats[3][128][2];  // per-layer per-channel (scale, shift)

// ---------------- packed f32x2 pack helper ----------------
__device__ __forceinline__ unsigned long long pk2(float lo, float hi) {
    unsigned long long r; asm("mov.b64 %0, {%1, %2};" : "=l"(r) : "f"(lo), "f"(hi)); return r;
}

// Fused per-pair FPS update: ONE asm block, all temps internal. Exact semantics
// identical to the passing R7/R9 path (unfused RN ops, same order).
__device__ __forceinline__ void upd2(unsigned long long X, unsigned long long Y, unsigned long long Z,
                                     unsigned long long NX, unsigned long long NY, unsigned long long NZ,
                                     float& d0, float& d1, float& m) {
    asm("{\n\t"
        ".reg .b64 dx, dy, dz, tx, ty, tz, s;\n\t"
        ".reg .f32 lo, hi;\n\t"
        "add.rn.f32x2 dx, %3, %6;\n\t"
        "add.rn.f32x2 dy, %4, %7;\n\t"
        "add.rn.f32x2 dz, %5, %8;\n\t"
        "mul.rn.f32x2 tx, dx, dx;\n\t"
        "mul.rn.f32x2 ty, dy, dy;\n\t"
        "mul.rn.f32x2 tz, dz, dz;\n\t"
        "add.rn.f32x2 s, tx, ty;\n\t"
        "add.rn.f32x2 s, s, tz;\n\t"
        "mov.b64 {lo, hi}, s;\n\t"
        "min.f32 %0, %0, lo;\n\t"
        "min.f32 %1, %1, hi;\n\t"
        "max.f32 %2, %2, %0;\n\t"
        "max.f32 %2, %2, %1;\n\t"
        "}"
        : "+f"(d0), "+f"(d1), "+f"(m)
        : "l"(X), "l"(Y), "l"(Z), "l"(NX), "l"(NY), "l"(NZ));
}

// ---------------- cluster helpers ----------------
__device__ __forceinline__ unsigned smem_u32(const void* p) {
    unsigned a;
    asm("{ .reg .u64 t; cvta.to.shared.u64 t, %1; cvt.u32.u64 %0, t; }" : "=r"(a) : "l"(p));
    return a;
}
__device__ __forceinline__ unsigned ctarank() {
    unsigned r; asm("mov.u32 %0, %%cluster_ctarank;" : "=r"(r)); return r;
}
__device__ __forceinline__ unsigned mapa_u32(unsigned addr, unsigned rank) {
    unsigned r; asm("mapa.shared::cluster.u32 %0, %1, %2;" : "=r"(r) : "r"(addr), "r"(rank));
    return r;
}
__device__ __forceinline__ void mbar_init(unsigned addr, unsigned cnt) {
    asm volatile("mbarrier.init.shared.b64 [%0], %1;" :: "r"(addr), "r"(cnt) : "memory");
}
__device__ __forceinline__ void st_cluster_u64(unsigned addr, unsigned long long v) {
    asm volatile("st.shared::cluster.u64 [%0], %1;" :: "r"(addr), "l"(v) : "memory");
}
__device__ __forceinline__ void mbar_arrive_cluster(unsigned addr) {
    asm volatile("mbarrier.arrive.release.cluster.shared::cluster.b64 _, [%0];"
                 :: "r"(addr) : "memory");
}
// sleep-hint wait (HW-sleep, not busy poll)
__device__ __forceinline__ void mbar_wait_cluster(unsigned addr, unsigned parity) {
    asm volatile(
        "{\n\t.reg .pred P;\n\t"
        "W_%=:\n\t"
        "mbarrier.try_wait.parity.acquire.cluster.shared::cta.b64 P, [%0], %1, 0x989680;\n\t"
        "@!P bra W_%=;\n\t}"
        :: "r"(addr), "r"(parity) : "memory");
}
__device__ __forceinline__ void cluster_sync_() {
    asm volatile("barrier.cluster.arrive.aligned;" ::: "memory");
    asm volatile("barrier.cluster.wait.aligned;" ::: "memory");
}

// ---------------- FPS v6: 2-CTA cluster per batch ----------------
// Each CTA keeps all 8192 coords in smem (centroid lookup) and register-owns
// 4096 points (4 pair-slots/thread). Per iter: halved local update + block
// combine in HIGH-priority warp 15 + 2x (st.shared::cluster + arrive.release)
// exchange; everyone waits with sleep-hint try_wait. Exact selection semantics.
__global__ void __launch_bounds__(512, 1) __cluster_dims__(CLS, 1, 1)
fps_kernel(const float* __restrict__ x, float* __restrict__ out_newx) {
    extern __shared__ float sm[];
    float* sx = sm;
    float* sy = sm + Nc;
    float* sz = sm + 2*Nc;
    __shared__ unsigned long long s_wred[2][16];   // per-warp keys, parity-buffered
    __shared__ unsigned long long s_ex[2][CLS];    // exchange slots [parity][rank]
    __shared__ unsigned long long s_mbar[2];       // parity mbarriers

    int b = blockIdx.x / CLS;
    unsigned rank = ctarank();
    int tid = threadIdx.x, lane = tid & 31, wid = tid >> 5;
    const float* xb = x + (size_t)b*Nc*3;

    unsigned mbarA[2] = { smem_u32(&s_mbar[0]), smem_u32(&s_mbar[1]) };
    unsigned exA = smem_u32(&s_ex[0][0]);
    if (tid == 0) { mbar_init(mbarA[0], CLS); mbar_init(mbarA[1], CLS); }

    for (int i = tid; i < Nc; i += 512) {
        sx[i] = xb[i*3+0];
        sy[i] = xb[i*3+1];
        sz[i] = xb[i*3+2];
    }
    __syncthreads();
    cluster_sync_();   // mbarriers + coords visible before any arrives

    // register-own pairs: global pair q = rank*2048 + tid + k*512, k=0..3
    unsigned long long Xr[4], Yr[4], Zr[4];
    int gbase = (int)rank * 2048;
#pragma unroll
    for (int k = 0; k < 4; k++) {
        int q = gbase + tid + k*512;
        Xr[k] = *(const unsigned long long*)&sx[2*q];
        Yr[k] = *(const unsigned long long*)&sy[2*q];
        Zr[k] = *(const unsigned long long*)&sz[2*q];
    }
    float dd[8];
#pragma unroll
    for (int i = 0; i < 8; i++) dd[i] = 1e10f;

    // hoisted remote/local exchange addresses (per parity)
    unsigned stA[2][CLS], arA[2][CLS];
#pragma unroll
    for (int p = 0; p < 2; p++)
#pragma unroll
        for (unsigned r2 = 0; r2 < CLS; r2++) {
            stA[p][r2] = mapa_u32(exA + (unsigned)(p*CLS + rank)*8u, r2);
            arA[p][r2] = mapa_u32(mbarA[p], r2);
        }

    int far = 0;
    for (int it = 0; it < Sc; ++it) {
        float cx = sx[far], cy = sy[far], cz = sz[far];
        if (rank == 0 && tid == 0) {
            float* o = &out_newx[((size_t)b*Sc + it)*3];
            o[0] = cx; o[1] = cy; o[2] = cz;
        }
        unsigned long long NX = pk2(-cx, -cx), NY = pk2(-cy, -cy), NZ = pk2(-cz, -cz);

        float m = -1.f;
#pragma unroll
        for (int k = 0; k < 4; k++)
            upd2(Xr[k], Yr[k], Zr[k], NX, NY, NZ, dd[2*k], dd[2*k+1], m);

        unsigned wmax = __reduce_max_sync(0xffffffffu, __float_as_uint(m));

        unsigned mask = 0u;
#pragma unroll
        for (int k = 0; k < 4; k++) {
            if (__float_as_uint(dd[2*k])   == wmax) mask |= 1u << (2*k);
            if (__float_as_uint(dd[2*k+1]) == wmax) mask |= 1u << (2*k+1);
        }
        unsigned cand = 0xFFFFFFFFu;
        if (mask) {
            int posn = __ffs(mask) - 1;   // 2k+b, smallest -> lowest global idx
            cand = (unsigned)(2*(gbase + tid + (posn >> 1)*512) + (posn & 1));
        }
        unsigned wc = __reduce_min_sync(0xffffffffu, cand);

        int p = it & 1;
        if (lane == 0)
            s_wred[p][wid] = ((unsigned long long)wmax << 32) | (unsigned)(Nc - 1 - wc);
        __syncthreads();

        // HIGH-priority warp 15 combines 16 warp keys and runs the exchange
        if (wid == 15) {
            unsigned long long e = s_wred[p][lane & 15];
            unsigned hi = (unsigned)(e >> 32);
            unsigned lo = (unsigned)(e & 0xFFFFFFFFull);
            unsigned M  = __reduce_max_sync(0xffffffffu, hi);
            unsigned r  = __reduce_max_sync(0xffffffffu, (hi == M) ? lo : 0u);
            if (lane == 0) {
                unsigned long long blk = ((unsigned long long)M << 32) | r;
                st_cluster_u64(stA[p][0], blk);
                st_cluster_u64(stA[p][1], blk);
                mbar_arrive_cluster(arA[p][0]);
                mbar_arrive_cluster(arA[p][1]);
            }
        }
        mbar_wait_cluster(mbarA[p], (unsigned)((it >> 1) & 1));

        unsigned long long e0 = s_ex[p][0], e1 = s_ex[p][1];
        unsigned long long best = (e1 > e0) ? e1 : e0;
        far = Nc - 1 - (int)(unsigned)(best & 0xFFFFFFFFull);
    }
    cluster_sync_();
}

// ---------------- ball query + group + center: one warp per centroid ----------------
__global__ void ball_kernel(const float* __restrict__ x, const float* __restrict__ newx) {
    int gw   = (blockIdx.x * blockDim.x + threadIdx.x) >> 5;
    int lane = threadIdx.x & 31;
    if (gw >= Bc*Sc) return;
    int b = gw >> 10;
    const float* xb = x + (size_t)b*Nc*3;

    float cx = newx[gw*3+0], cy = newx[gw*3+1], cz = newx[gw*3+2];
    float c2 = __fadd_rn(__fadd_rn(__fmul_rn(cx,cx), __fmul_rn(cy,cy)), __fmul_rn(cz,cz));

    int cnt = 0, firstIdx = -1;
    int pb = gw * Kc;

    for (int base = 0; base < Nc && cnt < Kc; base += 32) {
        int j = base + lane;
        float ax = xb[j*3+0], ay = xb[j*3+1], az = xb[j*3+2];
        float dot = __fadd_rn(__fadd_rn(__fmul_rn(cx,ax), __fmul_rn(cy,ay)), __fmul_rn(cz,az));
        float p2  = __fadd_rn(__fadd_rn(__fmul_rn(ax,ax), __fmul_rn(ay,ay)), __fmul_rn(az,az));
        float sq  = __fadd_rn(__fadd_rn(__fmul_rn(-2.0f, dot), c2), p2);
        bool in = !(sq > 0.04f);

        unsigned m = __ballot_sync(0xffffffffu, in);
        int pos = cnt + __popc(m & ((1u << lane) - 1u));
        if (in && pos < Kc) {
            g_h0[pb + pos]        = ax - cx;
            g_h0[Pc + pb + pos]   = ay - cy;
            g_h0[2*Pc + pb + pos] = az - cz;
        }
        if (firstIdx < 0 && m) firstIdx = base + __ffs(m) - 1;
        cnt += __popc(m);
    }
    cnt = min(cnt, Kc);
    if (lane >= cnt && firstIdx >= 0) {
        float ax = xb[firstIdx*3+0], ay = xb[firstIdx*3+1], az = xb[firstIdx*3+2];
        g_h0[pb + lane]        = ax - cx;
        g_h0[Pc + pb + lane]   = ay - cy;
        g_h0[2*Pc + pb + lane] = az - cz;
    }
}

// ---------------- layer 1: 3 -> 64 ----------------
__global__ void layer1_kernel(const float* __restrict__ W, const float* __restrict__ bb) {
    __shared__ float sW[64*3], sb[64];
    int tid = threadIdx.x;
    if (tid < 192) sW[tid] = W[tid];
    if (tid < 64)  sb[tid] = bb[tid];
    __syncthreads();

    int p = blockIdx.x * 256 + tid;
    float h0 = g_h0[p], h1 = g_h0[Pc + p], h2 = g_h0[2*Pc + p];
#pragma unroll
    for (int o = 0; o < 64; o++) {
        float y = fmaf(sW[o*3+2], h2, fmaf(sW[o*3+1], h1, fmaf(sW[o*3+0], h0, sb[o])));
        g_y1[(size_t)o*Pc + p] = y;
    }
}

// ---------------- init per-channel sums ----------------
__global__ void init_sums_kernel() {
    int i = threadIdx.x;
    if (i < 3*128*2) ((double*)g_sums)[i] = 0.0;
}

// ---------------- per-channel sum/sumsq reduction (layers 0,1) ----------------
__global__ void stats_kernel(int layer) {
    const float* y = (layer == 0) ? g_y1 : g_y2;
    int c = blockIdx.y;
    const float* yc = y + (size_t)c*Pc;

    float s = 0.f, q = 0.f;
    for (int i = blockIdx.x*blockDim.x + threadIdx.x; i < Pc; i += gridDim.x*blockDim.x) {
        float v = yc[i];
        s += v; q += v*v;
    }
    double ds = s, dq = q;
#pragma unroll
    for (int off = 16; off; off >>= 1) {
        ds += __shfl_down_sync(0xffffffffu, ds, off);
        dq += __shfl_down_sync(0xffffffffu, dq, off);
    }
    __shared__ double ssm[8], sqm[8];
    int w = threadIdx.x >> 5;
    if ((threadIdx.x & 31) == 0) { ssm[w] = ds; sqm[w] = dq; }
    __syncthreads();
    if (threadIdx.x == 0) {
        double a = 0.0, bq = 0.0;
#pragma unroll
        for (int i = 0; i < 8; i++) { a += ssm[i]; bq += sqm[i]; }
        atomicAdd(&g_sums[layer][c][0], a);
        atomicAdd(&g_sums[layer][c][1], bq);
    }
}

// ---------------- fold BN into scale/shift ----------------
__global__ void finalize_kernel(int layer, int C, const float* __restrict__ g, const float* __restrict__ be) {
    int c = threadIdx.x;
    if (c < C) {
        double n = (double)Pc;
        double mean = g_sums[layer][c][0] / n;
        double var  = g_sums[layer][c][1] / n - mean*mean;
        float invstd = (float)rsqrt(var + 1e-5);
        float scale = g[c] * invstd;
        float shift = fmaf(-(float)mean, scale, be[c]);
        g_stats[layer][c][0] = scale;
        g_stats[layer][c][1] = shift;
    }
}

// ---------------- layer 2: 64 -> 64 (norm+ReLU of y1 on the fly) ----------------
__global__ void layer2_kernel(const float* __restrict__ W, const float* __restrict__ bb) {
    __shared__ float sW[64*64];      // [c][o]
    __shared__ float sb[64], ssc[64], ssh[64];
    int tid = threadIdx.x;
    for (int i = tid; i < 4096; i += 256) {
        int c = i >> 6, o = i & 63;
        sW[i] = W[o*64 + c];
    }
    if (tid < 64) {
        sb[tid]  = bb[tid];
        ssc[tid] = g_stats[0][tid][0];
        ssh[tid] = g_stats[0][tid][1];
    }
    __syncthreads();

    int p = blockIdx.x * 256 + tid;
    float acc[64];
#pragma unroll
    for (int o = 0; o < 64; o++) acc[o] = sb[o];

    for (int c = 0; c < 64; c++) {
        float v = g_y1[(size_t)c*Pc + p];
        float h = fmaxf(fmaf(v, ssc[c], ssh[c]), 0.f);
        const float4* wr = (const float4*)(sW + c*64);
#pragma unroll
        for (int o4 = 0; o4 < 16; o4++) {
            float4 w = wr[o4];
            acc[o4*4+0] = fmaf(w.x, h, acc[o4*4+0]);
            acc[o4*4+1] = fmaf(w.y, h, acc[o4*4+1]);
            acc[o4*4+2] = fmaf(w.z, h, acc[o4*4+2]);
            acc[o4*4+3] = fmaf(w.w, h, acc[o4*4+3]);
        }
    }
#pragma unroll
    for (int o = 0; o < 64; o++) g_y2[(size_t)o*Pc + p] = acc[o];
}

// ---------------- layer 3 fused: 64 -> 128, per-centroid max/min + global stats ----------------
__global__ void layer3_kernel(const float* __restrict__ W, const float* __restrict__ bb) {
    int half = blockIdx.y;
    __shared__ float sW[64*64];
    __shared__ float sb[64], ssc[64], ssh[64];
    __shared__ double sSum[64], sSq[64];
    int tid = threadIdx.x, lane = tid & 31;
    for (int i = tid; i < 4096; i += 256) {
        int c = i >> 6, oo = i & 63;
        sW[i] = W[(half*64 + oo)*64 + c];
    }
    if (tid < 64) {
        sb[tid]  = bb[half*64 + tid];
        ssc[tid] = g_stats[1][tid][0];
        ssh[tid] = g_stats[1][tid][1];
        sSum[tid] = 0.0; sSq[tid] = 0.0;
    }
    __syncthreads();

    int p = blockIdx.x * 256 + tid;
    float acc[64];
#pragma unroll
    for (int o = 0; o < 64; o++) acc[o] = sb[o];

    for (int c = 0; c < 64; c++) {
        float v = g_y2[(size_t)c*Pc + p];
        float h = fmaxf(fmaf(v, ssc[c], ssh[c]), 0.f);
        const float4* wr = (const float4*)(sW + c*64);
#pragma unroll
        for (int o4 = 0; o4 < 16; o4++) {
            float4 w = wr[o4];
            acc[o4*4+0] = fmaf(w.x, h, acc[o4*4+0]);
            acc[o4*4+1] = fmaf(w.y, h, acc[o4*4+1]);
            acc[o4*4+2] = fmaf(w.z, h, acc[o4*4+2]);
            acc[o4*4+3] = fmaf(w.w, h, acc[o4*4+3]);
        }
    }

    int cent = p >> 5;
    float kmx0 = 0.f, kmx1 = 0.f, kmn0 = 0.f, kmn1 = 0.f;
    double ksm0 = 0.0, ksm1 = 0.0, ksq0 = 0.0, ksq1 = 0.0;
#pragma unroll 4
    for (int o = 0; o < 64; o++) {
        float v = acc[o];
        float mx = v, mn = v, s1 = v, s2 = v*v;
#pragma unroll
        for (int off = 16; off; off >>= 1) {
            mx = fmaxf(mx, __shfl_xor_sync(0xffffffffu, mx, off));
            mn = fminf(mn, __shfl_xor_sync(0xffffffffu, mn, off));
            s1 += __shfl_xor_sync(0xffffffffu, s1, off);
            s2 += __shfl_xor_sync(0xffffffffu, s2, off);
        }
        if (o == 2*lane)     { kmx0 = mx; kmn0 = mn; ksm0 = (double)s1; ksq0 = (double)s2; }
        if (o == 2*lane + 1) { kmx1 = mx; kmn1 = mn; ksm1 = (double)s1; ksq1 = (double)s2; }
    }
    size_t base = (size_t)cent*128 + half*64 + 2*lane;
    *(float2*)&g_max3[base] = make_float2(kmx0, kmx1);
    *(float2*)&g_min3[base] = make_float2(kmn0, kmn1);

    atomicAdd(&sSum[2*lane],   ksm0);
    atomicAdd(&sSum[2*lane+1], ksm1);
    atomicAdd(&sSq[2*lane],    ksq0);
    atomicAdd(&sSq[2*lane+1],  ksq1);
    __syncthreads();
    if (tid < 64) {
        atomicAdd(&g_sums[2][half*64 + tid][0], sSum[tid]);
        atomicAdd(&g_sums[2][half*64 + tid][1], sSq[tid]);
    }
}

// ---------------- final: affine + ReLU on pre-pooled extremes ----------------
__global__ void final_kernel(float* __restrict__ outf) {
    int bs = blockIdx.x;
    int o  = threadIdx.x;
    float sc = g_stats[2][o][0], sh = g_stats[2][o][1];
    float v = (sc >= 0.f) ? g_max3[(size_t)bs*128 + o] : g_min3[(size_t)bs*128 + o];
    outf[(size_t)bs*128 + o] = fmaxf(fmaf(v, sc, sh), 0.f);
}

// ---------------- launch ----------------
extern "C" void kernel_launch(void* const* d_in, const int* in_sizes, int n_in,
                              void* d_out, int out_size) {
    const float* x   = (const float*)d_in[0];
    const float* W1  = (const float*)d_in[1];
    const float* b1  = (const float*)d_in[2];
    const float* g1  = (const float*)d_in[3];
    const float* be1 = (const float*)d_in[4];
    const float* W2  = (const float*)d_in[5];
    const float* b2  = (const float*)d_in[6];
    const float* g2  = (const float*)d_in[7];
    const float* be2 = (const float*)d_in[8];
    const float* W3  = (const float*)d_in[9];
    const float* b3  = (const float*)d_in[10];
    const float* g3  = (const float*)d_in[11];
    const float* be3 = (const float*)d_in[12];

    float* out  = (float*)d_out;            // new_x: 8*1024*3
    float* outF = out + Bc*Sc*3;            // features: 8*1024*128

    size_t fps_smem = (size_t)(3*Nc)*sizeof(float);
    cudaFuncSetAttribute(fps_kernel, cudaFuncAttributeMaxDynamicSharedMemorySize, (int)fps_smem);

    fps_kernel<<<Bc*CLS, 512, fps_smem>>>(x, out);
    init_sums_kernel<<<1, 768>>>();
    ball_kernel<<<(Bc*Sc*32)/256, 256>>>(x, out);

    layer1_kernel<<<Pc/256, 256>>>(W1, b1);
    stats_kernel<<<dim3(64, 64), 256>>>(0);
    finalize_kernel<<<1, 128>>>(0, 64, g1, be1);

    layer2_kernel<<<Pc/256, 256>>>(W2, b2);
    stats_kernel<<<dim3(64, 64), 256>>>(1);
    finalize_kernel<<<1, 128>>>(1, 64, g2, be2);

    layer3_kernel<<<dim3(Pc/256, 2), 256>>>(W3, b3);
    finalize_kernel<<<1, 128>>>(2, 128, g3, be3);

    final_kernel<<<Bc*Sc, 128>>>(outF);
}

// round 12
// speedup vs baseline: 1.5435x; 1.5435x over previous
#include <cuda_runtime.h>
#include <cuda_bf16.h>

#define Bc 8
#define Nc 8192
#define Sc 1024
#define Kc 32
#define Pc (Bc*Sc*Kc)   // 262144 total grouped points

// ---------------- scratch (static device globals; no allocation) ----------------
__device__ float  g_h0[3*Pc];          // centered grouped coords, [c][P]
__device__ float  g_y1[64*Pc];         // 64 MiB
__device__ float  g_y2[64*Pc];         // 64 MiB
__device__ float  g_max3[Bc*Sc*128];   // per-centroid per-channel max of y3 (4 MiB)
__device__ float  g_min3[Bc*Sc*128];   // per-centroid per-channel min of y3 (4 MiB)
__device__ double g_sums[3][128][2];   // per-layer per-channel (sum, sumsq)
__device__ float  g_stats[3][128][2];  // per-layer per-channel (scale, shift)

// ---------------- packed f32x2 pack helper ----------------
__device__ __forceinline__ unsigned long long pk2(float lo, float hi) {
    unsigned long long r; asm("mov.b64 %0, {%1, %2};" : "=l"(r) : "f"(lo), "f"(hi)); return r;
}

// Fused per-pair FPS update: ONE asm block, all temps internal. Exact semantics
// identical to the passing R7/R9 path (unfused RN ops, same order).
__device__ __forceinline__ void upd2(unsigned long long X, unsigned long long Y, unsigned long long Z,
                                     unsigned long long NX, unsigned long long NY, unsigned long long NZ,
                                     float& d0, float& d1, float& m) {
    asm("{\n\t"
        ".reg .b64 dx, dy, dz, tx, ty, tz, s;\n\t"
        ".reg .f32 lo, hi;\n\t"
        "add.rn.f32x2 dx, %3, %6;\n\t"
        "add.rn.f32x2 dy, %4, %7;\n\t"
        "add.rn.f32x2 dz, %5, %8;\n\t"
        "mul.rn.f32x2 tx, dx, dx;\n\t"
        "mul.rn.f32x2 ty, dy, dy;\n\t"
        "mul.rn.f32x2 tz, dz, dz;\n\t"
        "add.rn.f32x2 s, tx, ty;\n\t"
        "add.rn.f32x2 s, s, tz;\n\t"
        "mov.b64 {lo, hi}, s;\n\t"
        "min.f32 %0, %0, lo;\n\t"
        "min.f32 %1, %1, hi;\n\t"
        "max.f32 %2, %2, %0;\n\t"
        "max.f32 %2, %2, %1;\n\t"
        "}"
        : "+f"(d0), "+f"(d1), "+f"(m)
        : "l"(X), "l"(Y), "l"(Z), "l"(NX), "l"(NY), "l"(NZ));
}

// ---------------- FPS v7: single block/batch + exact spatial pruning ----------------
// Points counting-sorted by 4x4x4 Morton cell (init, smem). Warp w owns sorted
// positions [512w, 512w+512) (~a 0.5 x 0.5 x 0.25 box). Per iteration a warp
// SKIPS the distance update when dmin(c, warp bbox)^2 (with conservative margin)
// >= U = warp's current max dd: then provably min(dd, d(p,c)) == dd for all its
// points, so dd registers and the cached candidate key stay exact. fminf over a
// set is order/subset-independent (exact selection of an input), so skipping
// preserves bit-exact dd. Tie-break = exact lowest ORIGINAL index among max-dd.
__global__ void __launch_bounds__(512, 1)
fps_kernel(const float* __restrict__ x, float* __restrict__ out_newx) {
    extern __shared__ float sm[];
    float* sx = sm;
    float* sy = sm + Nc;
    float* sz = sm + 2*Nc;
    int*   spidx = (int*)(sm + 3*Nc);                      // sorted orig indices
    unsigned long long* swb = (unsigned long long*)(spidx + Nc);  // [2][16] parity bufs
    __shared__ int s_cnt[64];

    int b = blockIdx.x, tid = threadIdx.x;
    int lane = tid & 31, wid = tid >> 5;
    const float* xb = x + (size_t)b*Nc*3;

    for (int i = tid; i < Nc; i += 512) {
        sx[i] = xb[i*3+0];
        sy[i] = xb[i*3+1];
        sz[i] = xb[i*3+2];
    }
    if (tid < 64) s_cnt[tid] = 0;
    __syncthreads();

    // ---- counting sort by Morton cell (init only) ----
    int rank16[16]; int cid16[16];
#pragma unroll
    for (int t = 0; t < 16; t++) {
        int i = tid + t*512;
        int ix = min((int)(sx[i]*4.f), 3);
        int iy = min((int)(sy[i]*4.f), 3);
        int iz = min((int)(sz[i]*4.f), 3);
        int cid = (ix&1) | ((iy&1)<<1) | ((iz&1)<<2)
                | ((ix>>1)<<3) | ((iy>>1)<<4) | ((iz>>1)<<5);
        cid16[t] = cid;
        rank16[t] = atomicAdd(&s_cnt[cid], 1);
    }
    __syncthreads();
    if (tid == 0) {
        int acc = 0;
#pragma unroll
        for (int c = 0; c < 64; c++) { int v = s_cnt[c]; s_cnt[c] = acc; acc += v; }
    }
    __syncthreads();
#pragma unroll
    for (int t = 0; t < 16; t++)
        spidx[s_cnt[cid16[t]] + rank16[t]] = tid + t*512;
    __syncthreads();

    // ---- register load (16 pts/thread via sorted indices) + warp bbox ----
    unsigned long long Xr[8], Yr[8], Zr[8];
    unsigned oi[8];            // two 16-bit orig indices per pair
    float lx0 = 1e30f, lx1 = -1e30f, ly0 = 1e30f, ly1 = -1e30f, lz0 = 1e30f, lz1 = -1e30f;
#pragma unroll
    for (int k = 0; k < 8; k++) {
        int pos = wid*512 + k*64 + lane*2;
        int i0 = spidx[pos], i1 = spidx[pos+1];
        float x0 = sx[i0], x1 = sx[i1];
        float y0 = sy[i0], y1 = sy[i1];
        float z0 = sz[i0], z1 = sz[i1];
        Xr[k] = pk2(x0, x1); Yr[k] = pk2(y0, y1); Zr[k] = pk2(z0, z1);
        oi[k] = (unsigned)i0 | ((unsigned)i1 << 16);
        lx0 = fminf(lx0, fminf(x0, x1)); lx1 = fmaxf(lx1, fmaxf(x0, x1));
        ly0 = fminf(ly0, fminf(y0, y1)); ly1 = fmaxf(ly1, fmaxf(y0, y1));
        lz0 = fminf(lz0, fminf(z0, z1)); lz1 = fmaxf(lz1, fmaxf(z0, z1));
    }
    // coords >= 0 -> uint order == float order
    float bx0 = __uint_as_float(__reduce_min_sync(0xffffffffu, __float_as_uint(lx0)));
    float bx1 = __uint_as_float(__reduce_max_sync(0xffffffffu, __float_as_uint(lx1)));
    float by0 = __uint_as_float(__reduce_min_sync(0xffffffffu, __float_as_uint(ly0)));
    float by1 = __uint_as_float(__reduce_max_sync(0xffffffffu, __float_as_uint(ly1)));
    float bz0 = __uint_as_float(__reduce_min_sync(0xffffffffu, __float_as_uint(lz0)));
    float bz1 = __uint_as_float(__reduce_max_sync(0xffffffffu, __float_as_uint(lz1)));

    float dd[16];
#pragma unroll
    for (int i = 0; i < 16; i++) dd[i] = 1e10f;

    // cached warp candidate key: (max-dd bits << 32) | (Nc-1-minOrigIdx).
    // init U = +inf -> first iteration always updates.
    unsigned long long kcache = 0x7F800000ULL << 32;

    int far = 0;
    for (int it = 0; it < Sc; ++it) {
        float cx = sx[far], cy = sy[far], cz = sz[far];
        if (tid == 0) {
            float* o = &out_newx[((size_t)b*Sc + it)*3];
            o[0] = cx; o[1] = cy; o[2] = cz;
        }

        // conservative box-distance skip test (warp-uniform)
        float tx = fmaxf(fmaxf(bx0 - cx, cx - bx1), 0.f);
        float ty = fmaxf(fmaxf(by0 - cy, cy - by1), 0.f);
        float tz = fmaxf(fmaxf(bz0 - cz, cz - bz1), 0.f);
        float d2 = fmaf(tx, tx, fmaf(ty, ty, tz*tz));
        float U  = __uint_as_float((unsigned)(kcache >> 32));

        if (!(d2 * 0.999997f >= U)) {
            unsigned long long NX = pk2(-cx, -cx), NY = pk2(-cy, -cy), NZ = pk2(-cz, -cz);
            float m = -1.f;
#pragma unroll
            for (int k = 0; k < 8; k++)
                upd2(Xr[k], Yr[k], Zr[k], NX, NY, NZ, dd[2*k], dd[2*k+1], m);

            unsigned wmax = __reduce_max_sync(0xffffffffu, __float_as_uint(m));
            unsigned cand = 0xFFFFFFFFu;
#pragma unroll
            for (int k = 0; k < 8; k++) {
                if (__float_as_uint(dd[2*k])   == wmax) cand = min(cand, oi[k] & 0xFFFFu);
                if (__float_as_uint(dd[2*k+1]) == wmax) cand = min(cand, oi[k] >> 16);
            }
            unsigned wc = __reduce_min_sync(0xffffffffu, cand);
            kcache = ((unsigned long long)wmax << 32) | (unsigned)(Nc - 1 - wc);
        }

        unsigned long long* buf = swb + (it & 1)*16;
        if (lane == 0) buf[wid] = kcache;
        __syncthreads();

        unsigned long long e = buf[lane & 15];
        unsigned hi = (unsigned)(e >> 32);
        unsigned lo = (unsigned)(e & 0xFFFFFFFFull);
        unsigned M  = __reduce_max_sync(0xffffffffu, hi);
        unsigned r  = __reduce_max_sync(0xffffffffu, (hi == M) ? lo : 0u);
        far = Nc - 1 - (int)r;
    }
}

// ---------------- ball query + group + center: one warp per centroid ----------------
__global__ void ball_kernel(const float* __restrict__ x, const float* __restrict__ newx) {
    int gw   = (blockIdx.x * blockDim.x + threadIdx.x) >> 5;
    int lane = threadIdx.x & 31;
    if (gw >= Bc*Sc) return;
    int b = gw >> 10;
    const float* xb = x + (size_t)b*Nc*3;

    float cx = newx[gw*3+0], cy = newx[gw*3+1], cz = newx[gw*3+2];
    float c2 = __fadd_rn(__fadd_rn(__fmul_rn(cx,cx), __fmul_rn(cy,cy)), __fmul_rn(cz,cz));

    int cnt = 0, firstIdx = -1;
    int pb = gw * Kc;

    for (int base = 0; base < Nc && cnt < Kc; base += 32) {
        int j = base + lane;
        float ax = xb[j*3+0], ay = xb[j*3+1], az = xb[j*3+2];
        float dot = __fadd_rn(__fadd_rn(__fmul_rn(cx,ax), __fmul_rn(cy,ay)), __fmul_rn(cz,az));
        float p2  = __fadd_rn(__fadd_rn(__fmul_rn(ax,ax), __fmul_rn(ay,ay)), __fmul_rn(az,az));
        float sq  = __fadd_rn(__fadd_rn(__fmul_rn(-2.0f, dot), c2), p2);
        bool in = !(sq > 0.04f);

        unsigned m = __ballot_sync(0xffffffffu, in);
        int pos = cnt + __popc(m & ((1u << lane) - 1u));
        if (in && pos < Kc) {
            g_h0[pb + pos]        = ax - cx;
            g_h0[Pc + pb + pos]   = ay - cy;
            g_h0[2*Pc + pb + pos] = az - cz;
        }
        if (firstIdx < 0 && m) firstIdx = base + __ffs(m) - 1;
        cnt += __popc(m);
    }
    cnt = min(cnt, Kc);
    if (lane >= cnt && firstIdx >= 0) {
        float ax = xb[firstIdx*3+0], ay = xb[firstIdx*3+1], az = xb[firstIdx*3+2];
        g_h0[pb + lane]        = ax - cx;
        g_h0[Pc + pb + lane]   = ay - cy;
        g_h0[2*Pc + pb + lane] = az - cz;
    }
}

// ---------------- layer 1: 3 -> 64 ----------------
__global__ void layer1_kernel(const float* __restrict__ W, const float* __restrict__ bb) {
    __shared__ float sW[64*3], sb[64];
    int tid = threadIdx.x;
    if (tid < 192) sW[tid] = W[tid];
    if (tid < 64)  sb[tid] = bb[tid];
    __syncthreads();

    int p = blockIdx.x * 256 + tid;
    float h0 = g_h0[p], h1 = g_h0[Pc + p], h2 = g_h0[2*Pc + p];
#pragma unroll
    for (int o = 0; o < 64; o++) {
        float y = fmaf(sW[o*3+2], h2, fmaf(sW[o*3+1], h1, fmaf(sW[o*3+0], h0, sb[o])));
        g_y1[(size_t)o*Pc + p] = y;
    }
}

// ---------------- init per-channel sums ----------------
__global__ void init_sums_kernel() {
    int i = threadIdx.x;
    if (i < 3*128*2) ((double*)g_sums)[i] = 0.0;
}

// ---------------- per-channel sum/sumsq reduction (layers 0,1) ----------------
__global__ void stats_kernel(int layer) {
    const float* y = (layer == 0) ? g_y1 : g_y2;
    int c = blockIdx.y;
    const float* yc = y + (size_t)c*Pc;

    float s = 0.f, q = 0.f;
    for (int i = blockIdx.x*blockDim.x + threadIdx.x; i < Pc; i += gridDim.x*blockDim.x) {
        float v = yc[i];
        s += v; q += v*v;
    }
    double ds = s, dq = q;
#pragma unroll
    for (int off = 16; off; off >>= 1) {
        ds += __shfl_down_sync(0xffffffffu, ds, off);
        dq += __shfl_down_sync(0xffffffffu, dq, off);
    }
    __shared__ double ssm[8], sqm[8];
    int w = threadIdx.x >> 5;
    if ((threadIdx.x & 31) == 0) { ssm[w] = ds; sqm[w] = dq; }
    __syncthreads();
    if (threadIdx.x == 0) {
        double a = 0.0, bq = 0.0;
#pragma unroll
        for (int i = 0; i < 8; i++) { a += ssm[i]; bq += sqm[i]; }
        atomicAdd(&g_sums[layer][c][0], a);
        atomicAdd(&g_sums[layer][c][1], bq);
    }
}

// ---------------- fold BN into scale/shift ----------------
__global__ void finalize_kernel(int layer, int C, const float* __restrict__ g, const float* __restrict__ be) {
    int c = threadIdx.x;
    if (c < C) {
        double n = (double)Pc;
        double mean = g_sums[layer][c][0] / n;
        double var  = g_sums[layer][c][1] / n - mean*mean;
        float invstd = (float)rsqrt(var + 1e-5);
        float scale = g[c] * invstd;
        float shift = fmaf(-(float)mean, scale, be[c]);
        g_stats[layer][c][0] = scale;
        g_stats[layer][c][1] = shift;
    }
}

// ---------------- layer 2: 64 -> 64 (norm+ReLU of y1 on the fly) ----------------
__global__ void layer2_kernel(const float* __restrict__ W, const float* __restrict__ bb) {
    __shared__ float sW[64*64];      // [c][o]
    __shared__ float sb[64], ssc[64], ssh[64];
    int tid = threadIdx.x;
    for (int i = tid; i < 4096; i += 256) {
        int c = i >> 6, o = i & 63;
        sW[i] = W[o*64 + c];
    }
    if (tid < 64) {
        sb[tid]  = bb[tid];
        ssc[tid] = g_stats[0][tid][0];
        ssh[tid] = g_stats[0][tid][1];
    }
    __syncthreads();

    int p = blockIdx.x * 256 + tid;
    float acc[64];
#pragma unroll
    for (int o = 0; o < 64; o++) acc[o] = sb[o];

    for (int c = 0; c < 64; c++) {
        float v = g_y1[(size_t)c*Pc + p];
        float h = fmaxf(fmaf(v, ssc[c], ssh[c]), 0.f);
        const float4* wr = (const float4*)(sW + c*64);
#pragma unroll
        for (int o4 = 0; o4 < 16; o4++) {
            float4 w = wr[o4];
            acc[o4*4+0] = fmaf(w.x, h, acc[o4*4+0]);
            acc[o4*4+1] = fmaf(w.y, h, acc[o4*4+1]);
            acc[o4*4+2] = fmaf(w.z, h, acc[o4*4+2]);
            acc[o4*4+3] = fmaf(w.w, h, acc[o4*4+3]);
        }
    }
#pragma unroll
    for (int o = 0; o < 64; o++) g_y2[(size_t)o*Pc + p] = acc[o];
}

// ---------------- layer 3 fused: 64 -> 128, per-centroid max/min + global stats ----------------
__global__ void layer3_kernel(const float* __restrict__ W, const float* __restrict__ bb) {
    int half = blockIdx.y;
    __shared__ float sW[64*64];
    __shared__ float sb[64], ssc[64], ssh[64];
    __shared__ double sSum[64], sSq[64];
    int tid = threadIdx.x, lane = tid & 31;
    for (int i = tid; i < 4096; i += 256) {
        int c = i >> 6, oo = i & 63;
        sW[i] = W[(half*64 + oo)*64 + c];
    }
    if (tid < 64) {
        sb[tid]  = bb[half*64 + tid];
        ssc[tid] = g_stats[1][tid][0];
        ssh[tid] = g_stats[1][tid][1];
        sSum[tid] = 0.0; sSq[tid] = 0.0;
    }
    __syncthreads();

    int p = blockIdx.x * 256 + tid;
    float acc[64];
#pragma unroll
    for (int o = 0; o < 64; o++) acc[o] = sb[o];

    for (int c = 0; c < 64; c++) {
        float v = g_y2[(size_t)c*Pc + p];
        float h = fmaxf(fmaf(v, ssc[c], ssh[c]), 0.f);
        const float4* wr = (const float4*)(sW + c*64);
#pragma unroll
        for (int o4 = 0; o4 < 16; o4++) {
            float4 w = wr[o4];
            acc[o4*4+0] = fmaf(w.x, h, acc[o4*4+0]);
            acc[o4*4+1] = fmaf(w.y, h, acc[o4*4+1]);
            acc[o4*4+2] = fmaf(w.z, h, acc[o4*4+2]);
            acc[o4*4+3] = fmaf(w.w, h, acc[o4*4+3]);
        }
    }

    int cent = p >> 5;
    float kmx0 = 0.f, kmx1 = 0.f, kmn0 = 0.f, kmn1 = 0.f;
    double ksm0 = 0.0, ksm1 = 0.0, ksq0 = 0.0, ksq1 = 0.0;
#pragma unroll 4
    for (int o = 0; o < 64; o++) {
        float v = acc[o];
        float mx = v, mn = v, s1 = v, s2 = v*v;
#pragma unroll
        for (int off = 16; off; off >>= 1) {
            mx = fmaxf(mx, __shfl_xor_sync(0xffffffffu, mx, off));
            mn = fminf(mn, __shfl_xor_sync(0xffffffffu, mn, off));
            s1 += __shfl_xor_sync(0xffffffffu, s1, off);
            s2 += __shfl_xor_sync(0xffffffffu, s2, off);
        }
        if (o == 2*lane)     { kmx0 = mx; kmn0 = mn; ksm0 = (double)s1; ksq0 = (double)s2; }
        if (o == 2*lane + 1) { kmx1 = mx; kmn1 = mn; ksm1 = (double)s1; ksq1 = (double)s2; }
    }
    size_t base = (size_t)cent*128 + half*64 + 2*lane;
    *(float2*)&g_max3[base] = make_float2(kmx0, kmx1);
    *(float2*)&g_min3[base] = make_float2(kmn0, kmn1);

    atomicAdd(&sSum[2*lane],   ksm0);
    atomicAdd(&sSum[2*lane+1], ksm1);
    atomicAdd(&sSq[2*lane],    ksq0);
    atomicAdd(&sSq[2*lane+1],  ksq1);
    __syncthreads();
    if (tid < 64) {
        atomicAdd(&g_sums[2][half*64 + tid][0], sSum[tid]);
        atomicAdd(&g_sums[2][half*64 + tid][1], sSq[tid]);
    }
}

// ---------------- final: affine + ReLU on pre-pooled extremes ----------------
__global__ void final_kernel(float* __restrict__ outf) {
    int bs = blockIdx.x;
    int o  = threadIdx.x;
    float sc = g_stats[2][o][0], sh = g_stats[2][o][1];
    float v = (sc >= 0.f) ? g_max3[(size_t)bs*128 + o] : g_min3[(size_t)bs*128 + o];
    outf[(size_t)bs*128 + o] = fmaxf(fmaf(v, sc, sh), 0.f);
}

// ---------------- launch ----------------
extern "C" void kernel_launch(void* const* d_in, const int* in_sizes, int n_in,
                              void* d_out, int out_size) {
    const float* x   = (const float*)d_in[0];
    const float* W1  = (const float*)d_in[1];
    const float* b1  = (const float*)d_in[2];
    const float* g1  = (const float*)d_in[3];
    const float* be1 = (const float*)d_in[4];
    const float* W2  = (const float*)d_in[5];
    const float* b2  = (const float*)d_in[6];
    const float* g2  = (const float*)d_in[7];
    const float* be2 = (const float*)d_in[8];
    const float* W3  = (const float*)d_in[9];
    const float* b3  = (const float*)d_in[10];
    const float* g3  = (const float*)d_in[11];
    const float* be3 = (const float*)d_in[12];

    float* out  = (float*)d_out;            // new_x: 8*1024*3
    float* outF = out + Bc*Sc*3;            // features: 8*1024*128

    // 3*Nc coords + Nc sorted-index ints + 2*16 u64 parity buffers
    size_t fps_smem = (size_t)(3*Nc)*sizeof(float) + (size_t)Nc*sizeof(int)
                    + 32*sizeof(unsigned long long);
    cudaFuncSetAttribute(fps_kernel, cudaFuncAttributeMaxDynamicSharedMemorySize, (int)fps_smem);

    fps_kernel<<<Bc, 512, fps_smem>>>(x, out);
    init_sums_kernel<<<1, 768>>>();
    ball_kernel<<<(Bc*Sc*32)/256, 256>>>(x, out);

    layer1_kernel<<<Pc/256, 256>>>(W1, b1);
    stats_kernel<<<dim3(64, 64), 256>>>(0);
    finalize_kernel<<<1, 128>>>(0, 64, g1, be1);

    layer2_kernel<<<Pc/256, 256>>>(W2, b2);
    stats_kernel<<<dim3(64, 64), 256>>>(1);
    finalize_kernel<<<1, 128>>>(1, 64, g2, be2);

    layer3_kernel<<<dim3(Pc/256, 2), 256>>>(W3, b3);
    finalize_kernel<<<1, 128>>>(2, 128, g3, be3);

    final_kernel<<<Bc*Sc, 128>>>(outF);
}